// round 3
// baseline (speedup 1.0000x reference)
#include <cuda_runtime.h>

#define N_NODES 100000
#define N_EDGES 3200000
#define HID 32
#define NCONV 16
#define SCAN_T 256
#define SCAN_NBLK ((N_NODES + SCAN_T - 1) / SCAN_T)   // 391

// ---- device scratch (static globals; no allocation) ----
__device__ int   g_deg[N_NODES];
__device__ int   g_cursor[N_NODES];
__device__ int   g_rowptr[N_NODES + 1];
__device__ float g_invdeg[N_NODES];
__device__ int   g_csr[N_EDGES];
__device__ float g_bufA[N_NODES * HID];
__device__ float g_bufB[N_NODES * HID];
__device__ float g_colsum[(NCONV + 1) * HID];
__device__ float g_zexp[N_NODES];
__device__ float g_S[1];
__device__ int   g_is64;
__device__ int   g_bsum[SCAN_NBLK];
__device__ int   g_boff[SCAN_NBLK];

// ---------------------------------------------------------------------------
// dtype detect: if edge_index is int64 (LE), every odd 32-bit word is 0
// (values in [0, 1e5)). If int32, odd words are random node ids.
__global__ void detect_kernel(const unsigned int* __restrict__ raw) {
    __shared__ int any;
    if (threadIdx.x == 0) any = 0;
    __syncthreads();
    unsigned v = raw[2 * threadIdx.x + 1 + threadIdx.x * 9973 * 2];
    if (v != 0u) atomicOr(&any, 1);
    __syncthreads();
    if (threadIdx.x == 0) g_is64 = any ? 0 : 1;
}

__global__ void init_kernel() {
    int i = blockIdx.x * blockDim.x + threadIdx.x;
    if (i < N_NODES) { g_deg[i] = 0; g_cursor[i] = 0; }
    if (i < (NCONV + 1) * HID) g_colsum[i] = (i < HID) ? 1.0f : 0.0f;
    if (i == 0) g_S[0] = 0.0f;
}

__device__ __forceinline__ int load_edge(const void* p, long long idx) {
    if (g_is64) return (int)((const long long*)p)[idx];
    return ((const int*)p)[idx];
}

__global__ void hist_kernel(const void* __restrict__ ei) {
    int i = blockIdx.x * blockDim.x + threadIdx.x;
    if (i < N_EDGES) {
        int d = load_edge(ei, (long long)N_EDGES + i);
        if ((unsigned)d < N_NODES) atomicAdd(&g_deg[d], 1);
    }
}

// ---- 3-phase scan of g_deg -> g_rowptr (exclusive) + g_invdeg ------------
__global__ void scan_partial_kernel() {
    int i = blockIdx.x * SCAN_T + threadIdx.x;
    int v = (i < N_NODES) ? g_deg[i] : 0;
    int lane = threadIdx.x & 31, w = threadIdx.x >> 5;
#pragma unroll
    for (int o = 16; o; o >>= 1) v += __shfl_xor_sync(0xffffffffu, v, o);
    __shared__ int ws[SCAN_T / 32];
    if (lane == 0) ws[w] = v;
    __syncthreads();
    if (threadIdx.x == 0) {
        int t = 0;
#pragma unroll
        for (int k = 0; k < SCAN_T / 32; ++k) t += ws[k];
        g_bsum[blockIdx.x] = t;
    }
}

__global__ void scan_bsum_kernel() {   // 1 block, 512 threads, 391 values
    __shared__ int sh[512];
    int t = threadIdx.x;
    sh[t] = (t < SCAN_NBLK) ? g_bsum[t] : 0;
    __syncthreads();
    // Hillis-Steele inclusive scan over 512
    for (int o = 1; o < 512; o <<= 1) {
        int v = (t >= o) ? sh[t - o] : 0;
        __syncthreads();
        sh[t] += v;
        __syncthreads();
    }
    if (t < SCAN_NBLK) g_boff[t] = sh[t] - g_bsum[t];   // exclusive
}

__global__ void scan_write_kernel() {
    int b = blockIdx.x;
    int i = b * SCAN_T + threadIdx.x;
    int d = (i < N_NODES) ? g_deg[i] : 0;
    int lane = threadIdx.x & 31, w = threadIdx.x >> 5;
    int v = d;
#pragma unroll
    for (int o = 1; o < 32; o <<= 1) {
        int u = __shfl_up_sync(0xffffffffu, v, o);
        if (lane >= o) v += u;
    }
    __shared__ int ws[SCAN_T / 32];
    if (lane == 31) ws[w] = v;
    __syncthreads();
    int woff = 0;
    for (int k = 0; k < w; ++k) woff += ws[k];
    int excl = g_boff[b] + woff + v - d;
    if (i < N_NODES) {
        g_rowptr[i] = excl;
        g_invdeg[i] = 1.0f / (float)max(d, 1);
        if (i == N_NODES - 1) g_rowptr[N_NODES] = excl + d;
    }
}

__global__ void fill_kernel(const void* __restrict__ ei) {
    int i = blockIdx.x * blockDim.x + threadIdx.x;
    if (i < N_EDGES) {
        int s = load_edge(ei, i);
        int d = load_edge(ei, (long long)N_EDGES + i);
        if ((unsigned)d >= N_NODES || (unsigned)s >= N_NODES) return;
        int p = atomicAdd(&g_cursor[d], 1);
        g_csr[g_rowptr[d] + p] = s;
    }
}

// ---------------------------------------------------------------------------
// proj_in: x[N,4] -> inner-softmax(avg@A_in + x@B_in) [N,32]. One warp/node.
__global__ void __launch_bounds__(256) proj_kernel(
    const float* __restrict__ x, const float* __restrict__ Ain,
    const float* __restrict__ Bin, float* __restrict__ out) {
    int lane = threadIdx.x & 31, wid = threadIdx.x >> 5;
    int n = blockIdx.x * 8 + wid;
    if (n >= N_NODES) return;
    int beg = g_rowptr[n], end = g_rowptr[n + 1];
    int gb = lane >> 2, ft = lane & 3;
    float sum = 0.0f;
    for (int base = beg; base < end; base += 8) {
        int j = base + gb;
        if (j < end) {
            int s = __ldg(&g_csr[j]);
            sum += __ldg(&x[s * 4 + ft]);
        }
    }
    sum += __shfl_xor_sync(0xffffffffu, sum, 4);
    sum += __shfl_xor_sync(0xffffffffu, sum, 8);
    sum += __shfl_xor_sync(0xffffffffu, sum, 16);
    float invd = g_invdeg[n];
    float a0 = __shfl_sync(0xffffffffu, sum, 0) * invd;
    float a1 = __shfl_sync(0xffffffffu, sum, 1) * invd;
    float a2 = __shfl_sync(0xffffffffu, sum, 2) * invd;
    float a3 = __shfl_sync(0xffffffffu, sum, 3) * invd;
    float4 xv = *(const float4*)&x[n * 4];
    float acc = a0 * __ldg(&Ain[lane])      + a1 * __ldg(&Ain[32 + lane])
              + a2 * __ldg(&Ain[64 + lane]) + a3 * __ldg(&Ain[96 + lane])
              + xv.x * __ldg(&Bin[lane])      + xv.y * __ldg(&Bin[32 + lane])
              + xv.z * __ldg(&Bin[64 + lane]) + xv.w * __ldg(&Bin[96 + lane]);
    float mx = acc;
#pragma unroll
    for (int o = 16; o; o >>= 1) mx = fmaxf(mx, __shfl_xor_sync(0xffffffffu, mx, o));
    float e = __expf(acc - mx);
    float ss = e;
#pragma unroll
    for (int o = 16; o; o >>= 1) ss += __shfl_xor_sync(0xffffffffu, ss, o);
    out[n * HID + lane] = e / ss;
}

// ---------------------------------------------------------------------------
// hidden conv layer. High-MLP gather: one coalesced csr load per 32 neighbors
// (indices spread across lanes, distributed by shfl), then 2 predicated
// batches of 16 independent row-gathers (MLP=16).
__global__ void __launch_bounds__(256) conv_kernel(
    const float* __restrict__ Ein, float* __restrict__ Eout,
    const float* __restrict__ Wa, const float* __restrict__ Wb,
    const float* __restrict__ cs_in, float* __restrict__ cs_out) {
    int lane = threadIdx.x & 31, wid = threadIdx.x >> 5;
    float WaR[HID], WbR[HID];
#pragma unroll
    for (int k = 0; k < HID; ++k) {
        WaR[k] = __ldg(&Wa[k * HID + lane]);
        WbR[k] = __ldg(&Wb[k * HID + lane]);
    }
    float invS = 1.0f / cs_in[lane];
    float colacc = 0.0f;

    for (int n = blockIdx.x * 8 + wid; n < N_NODES; n += gridDim.x * 8) {
        int beg = g_rowptr[n], end = g_rowptr[n + 1];
        float sum = 0.0f;
        for (int base = beg; base < end; base += 32) {
            int rem = end - base;
            int cnt = min(32, rem);
            int myi = (lane < cnt) ? __ldg(&g_csr[base + lane]) : 0;
#pragma unroll
            for (int k0 = 0; k0 < 32; k0 += 16) {
                if (k0 < cnt) {
                    float v[16];
#pragma unroll
                    for (int j = 0; j < 16; ++j) {
                        int s = __shfl_sync(0xffffffffu, myi, k0 + j);
                        v[j] = (k0 + j < cnt) ? __ldg(&Ein[s * HID + lane]) : 0.0f;
                    }
                    float p = 0.0f;
#pragma unroll
                    for (int j = 0; j < 16; ++j) p += v[j];
                    sum += p;
                }
            }
        }
        float avg = sum * (g_invdeg[n] * invS);
        float xd = __ldg(&Ein[n * HID + lane]) * invS;
        float acc = 0.0f;
#pragma unroll
        for (int k = 0; k < HID; ++k) {
            acc = fmaf(__shfl_sync(0xffffffffu, avg, k), WaR[k], acc);
            acc = fmaf(__shfl_sync(0xffffffffu, xd, k), WbR[k], acc);
        }
        float mx = acc;
#pragma unroll
        for (int o = 16; o; o >>= 1) mx = fmaxf(mx, __shfl_xor_sync(0xffffffffu, mx, o));
        float e = __expf(acc - mx);
        float ss = e;
#pragma unroll
        for (int o = 16; o; o >>= 1) ss += __shfl_xor_sync(0xffffffffu, ss, o);
        float E = __expf(e / ss);
        Eout[n * HID + lane] = E;
        colacc += E;
    }

    __shared__ float sred[8][HID];
    sred[wid][lane] = colacc;
    __syncthreads();
    if (wid == 0) {
        float t = sred[0][lane];
#pragma unroll
        for (int i = 1; i < 8; ++i) t += sred[i][lane];
        atomicAdd(&cs_out[lane], t);
    }
}

// ---------------------------------------------------------------------------
__global__ void __launch_bounds__(256) out_z_kernel(
    const float* __restrict__ E, const float* __restrict__ cs,
    const float* __restrict__ Wout, const float* __restrict__ bout) {
    int lane = threadIdx.x & 31, wid = threadIdx.x >> 5;
    float w = __ldg(&Wout[lane]) / cs[lane];
    float b = __ldg(bout);
    float acc = 0.0f;
    for (int n = blockIdx.x * 8 + wid; n < N_NODES; n += gridDim.x * 8) {
        float v = E[n * HID + lane] * w;
#pragma unroll
        for (int o = 16; o; o >>= 1) v += __shfl_xor_sync(0xffffffffu, v, o);
        float e = __expf(v + b);
        if (lane == 0) { g_zexp[n] = e; acc += e; }
    }
    __shared__ float sred[8];
    if (lane == 0) sred[wid] = acc;
    __syncthreads();
    if (threadIdx.x == 0) {
        float t = 0.0f;
#pragma unroll
        for (int i = 0; i < 8; ++i) t += sred[i];
        atomicAdd(g_S, t);
    }
}

__global__ void out_norm_kernel(float* __restrict__ out) {
    int i = blockIdx.x * blockDim.x + threadIdx.x;
    if (i < N_NODES) out[i] = g_zexp[i] / g_S[0];
}

// ---------------------------------------------------------------------------
extern "C" void kernel_launch(void* const* d_in, const int* in_sizes, int n_in,
                              void* d_out, int out_size) {
    const float* x     = (const float*)d_in[0];
    const void*  ei    = d_in[1];                    // [2, N_EDGES] int32 or int64
    const float* Ain   = (const float*)d_in[2];
    const float* Bin   = (const float*)d_in[3];
    const float* Aconv = (const float*)d_in[4];      // [16,32,32]
    const float* Bconv = (const float*)d_in[5];
    const float* Wout  = (const float*)d_in[6];
    const float* bout  = (const float*)d_in[7];
    float* out         = (float*)d_out;

    float *pA, *pB, *pcs;
    cudaGetSymbolAddress((void**)&pA, g_bufA);
    cudaGetSymbolAddress((void**)&pB, g_bufB);
    cudaGetSymbolAddress((void**)&pcs, g_colsum);

    detect_kernel<<<1, 64>>>((const unsigned int*)ei);
    init_kernel<<<(N_NODES + 255) / 256, 256>>>();
    hist_kernel<<<(N_EDGES + 255) / 256, 256>>>(ei);
    scan_partial_kernel<<<SCAN_NBLK, SCAN_T>>>();
    scan_bsum_kernel<<<1, 512>>>();
    scan_write_kernel<<<SCAN_NBLK, SCAN_T>>>();
    fill_kernel<<<(N_EDGES + 255) / 256, 256>>>(ei);

    proj_kernel<<<(N_NODES + 7) / 8, 256>>>(x, Ain, Bin, pA);

    float* bi = pA;
    float* bo = pB;
    for (int l = 0; l < NCONV; ++l) {
        conv_kernel<<<304, 256>>>(bi, bo,
                                  Aconv + l * HID * HID, Bconv + l * HID * HID,
                                  pcs + l * HID, pcs + (l + 1) * HID);
        float* t = bi; bi = bo; bo = t;
    }

    out_z_kernel<<<592, 256>>>(bi, pcs + NCONV * HID, Wout, bout);
    out_norm_kernel<<<(N_NODES + 255) / 256, 256>>>(out);
}

// round 4
// speedup vs baseline: 1.5799x; 1.5799x over previous
#include <cuda_runtime.h>

#define N_NODES 100000
#define N_EDGES 3200000
#define HID 32
#define NCONV 16

// ---- device scratch (static globals; no allocation) ----
__device__ int   g_deg[N_NODES];
__device__ int   g_cursor[N_NODES];
__device__ int   g_rowptr[N_NODES + 1];
__device__ float g_invdeg[N_NODES];
__device__ int   g_csr[N_EDGES];
__device__ float g_bufA[N_NODES * HID];
__device__ float g_bufB[N_NODES * HID];
__device__ float g_colsum[(NCONV + 1) * HID];
__device__ float g_zexp[N_NODES];
__device__ float g_S[1];
__device__ int   g_is64;

// ---------------------------------------------------------------------------
// init + dtype detect. If edge_index is int64 (LE), every odd 32-bit word is 0.
__global__ void init_kernel(const unsigned int* __restrict__ raw) {
    int i = blockIdx.x * blockDim.x + threadIdx.x;
    if (i < N_NODES) { g_deg[i] = 0; g_cursor[i] = 0; }
    if (i < (NCONV + 1) * HID) g_colsum[i] = (i < HID) ? 1.0f : 0.0f;
    if (i == 0) g_S[0] = 0.0f;
    if (blockIdx.x == 0) {
        __shared__ int any;
        if (threadIdx.x == 0) any = 0;
        __syncthreads();
        if (threadIdx.x < 64) {
            unsigned v = raw[2 * threadIdx.x + 1 + threadIdx.x * 9973 * 2];
            if (v != 0u) atomicOr(&any, 1);
        }
        __syncthreads();
        if (threadIdx.x == 0) g_is64 = any ? 0 : 1;
    }
}

__device__ __forceinline__ int load_edge(const void* p, long long idx) {
    if (g_is64) return (int)((const long long*)p)[idx];
    return ((const int*)p)[idx];
}

__global__ void hist_kernel(const void* __restrict__ ei) {
    int i = blockIdx.x * blockDim.x + threadIdx.x;
    if (i < N_EDGES) {
        int d = load_edge(ei, (long long)N_EDGES + i);
        if ((unsigned)d < N_NODES) atomicAdd(&g_deg[d], 1);
    }
}

// ---- single-block coalesced scan: g_deg -> g_rowptr (exclusive) + invdeg ----
__global__ void scan_kernel() {
    __shared__ int ws[32];
    __shared__ int s_carry;
    int t = threadIdx.x, lane = t & 31, w = t >> 5;
    if (t == 0) s_carry = 0;
    __syncthreads();
    const int4* deg4 = (const int4*)g_deg;
    const int NI4 = N_NODES / 4;             // 25000 (exact)
    for (int c = 0; c < (NI4 + 1023) / 1024; ++c) {
        int i4 = c * 1024 + t;
        int4 d = (i4 < NI4) ? deg4[i4] : make_int4(0, 0, 0, 0);
        int tsum = d.x + d.y + d.z + d.w;
        int v = tsum;
#pragma unroll
        for (int o = 1; o < 32; o <<= 1) {
            int u = __shfl_up_sync(0xffffffffu, v, o);
            if (lane >= o) v += u;
        }
        if (lane == 31) ws[w] = v;
        __syncthreads();
        if (w == 0) {
            int s = ws[lane];
#pragma unroll
            for (int o = 1; o < 32; o <<= 1) {
                int u = __shfl_up_sync(0xffffffffu, s, o);
                if (lane >= o) s += u;
            }
            ws[lane] = s;
        }
        __syncthreads();
        int excl = s_carry + (w ? ws[w - 1] : 0) + v - tsum;
        if (i4 < NI4) {
            int base = i4 * 4;
            int4 rp;
            rp.x = excl; rp.y = excl + d.x; rp.z = rp.y + d.y; rp.w = rp.z + d.z;
            *(int4*)&g_rowptr[base] = rp;
            float4 iv;
            iv.x = 1.0f / (float)max(d.x, 1);
            iv.y = 1.0f / (float)max(d.y, 1);
            iv.z = 1.0f / (float)max(d.z, 1);
            iv.w = 1.0f / (float)max(d.w, 1);
            *(float4*)&g_invdeg[base] = iv;
        }
        __syncthreads();
        if (t == 0) s_carry += ws[31];
        __syncthreads();
    }
    if (t == 0) g_rowptr[N_NODES] = s_carry;
}

__global__ void fill_kernel(const void* __restrict__ ei) {
    int i = blockIdx.x * blockDim.x + threadIdx.x;
    if (i < N_EDGES) {
        int s = load_edge(ei, i);
        int d = load_edge(ei, (long long)N_EDGES + i);
        if ((unsigned)d >= N_NODES || (unsigned)s >= N_NODES) return;
        int p = atomicAdd(&g_cursor[d], 1);
        g_csr[g_rowptr[d] + p] = s;
    }
}

// ---------------------------------------------------------------------------
// proj_in: x[N,4] -> inner-softmax(avg@A_in + x@B_in) [N,32]. One warp/node.
__global__ void __launch_bounds__(256) proj_kernel(
    const float* __restrict__ x, const float* __restrict__ Ain,
    const float* __restrict__ Bin, float* __restrict__ out) {
    int lane = threadIdx.x & 31, wid = threadIdx.x >> 5;
    int n = blockIdx.x * 8 + wid;
    if (n >= N_NODES) return;
    int beg = g_rowptr[n], end = g_rowptr[n + 1];
    int gb = lane >> 2, ft = lane & 3;
    float sum = 0.0f;
    for (int base = beg; base < end; base += 8) {
        int j = base + gb;
        if (j < end) {
            int s = __ldg(&g_csr[j]);
            sum += __ldg(&x[s * 4 + ft]);
        }
    }
    sum += __shfl_xor_sync(0xffffffffu, sum, 4);
    sum += __shfl_xor_sync(0xffffffffu, sum, 8);
    sum += __shfl_xor_sync(0xffffffffu, sum, 16);
    float invd = g_invdeg[n];
    float a0 = __shfl_sync(0xffffffffu, sum, 0) * invd;
    float a1 = __shfl_sync(0xffffffffu, sum, 1) * invd;
    float a2 = __shfl_sync(0xffffffffu, sum, 2) * invd;
    float a3 = __shfl_sync(0xffffffffu, sum, 3) * invd;
    float4 xv = *(const float4*)&x[n * 4];
    float acc = a0 * __ldg(&Ain[lane])      + a1 * __ldg(&Ain[32 + lane])
              + a2 * __ldg(&Ain[64 + lane]) + a3 * __ldg(&Ain[96 + lane])
              + xv.x * __ldg(&Bin[lane])      + xv.y * __ldg(&Bin[32 + lane])
              + xv.z * __ldg(&Bin[64 + lane]) + xv.w * __ldg(&Bin[96 + lane]);
    float mx = acc;
#pragma unroll
    for (int o = 16; o; o >>= 1) mx = fmaxf(mx, __shfl_xor_sync(0xffffffffu, mx, o));
    float e = __expf(acc - mx);
    float ss = e;
#pragma unroll
    for (int o = 16; o; o >>= 1) ss += __shfl_xor_sync(0xffffffffu, ss, o);
    out[n * HID + lane] = e / ss;
}

// ---------------------------------------------------------------------------
// hidden conv layer. Weights live in SHARED memory (frees ~64 regs/thread ->
// high occupancy -> gather latency hidden by warp count + MLP-8 batches).
__global__ void __launch_bounds__(256) conv_kernel(
    const float* __restrict__ Ein, float* __restrict__ Eout,
    const float* __restrict__ Wa, const float* __restrict__ Wb,
    const float* __restrict__ cs_in, float* __restrict__ cs_out) {
    __shared__ float sWa[HID][HID];
    __shared__ float sWb[HID][HID];
    __shared__ float sred[8][HID];
    int tid = threadIdx.x;
    int lane = tid & 31, wid = tid >> 5;
#pragma unroll
    for (int i = tid; i < HID * HID; i += 256) {
        ((float*)sWa)[i] = __ldg(&Wa[i]);
        ((float*)sWb)[i] = __ldg(&Wb[i]);
    }
    __syncthreads();
    float invS = 1.0f / cs_in[lane];
    float colacc = 0.0f;

    for (int n = blockIdx.x * 8 + wid; n < N_NODES; n += gridDim.x * 8) {
        int beg = g_rowptr[n], end = g_rowptr[n + 1];
        float sum = 0.0f;
        for (int base = beg; base < end; base += 32) {
            int cnt = min(32, end - base);
            int myi = (lane < cnt) ? __ldg(&g_csr[base + lane]) : 0;
#pragma unroll
            for (int k0 = 0; k0 < 32; k0 += 8) {
                if (k0 < cnt) {
                    float v[8];
#pragma unroll
                    for (int j = 0; j < 8; ++j) {
                        int s = __shfl_sync(0xffffffffu, myi, k0 + j);
                        v[j] = (k0 + j < cnt) ? __ldg(&Ein[s * HID + lane]) : 0.0f;
                    }
                    sum += ((v[0] + v[1]) + (v[2] + v[3])) +
                           ((v[4] + v[5]) + (v[6] + v[7]));
                }
            }
        }
        float avg = sum * (g_invdeg[n] * invS);
        float xd = __ldg(&Ein[n * HID + lane]) * invS;
        float acc = 0.0f;
#pragma unroll
        for (int k = 0; k < HID; ++k) {
            acc = fmaf(__shfl_sync(0xffffffffu, avg, k), sWa[k][lane], acc);
            acc = fmaf(__shfl_sync(0xffffffffu, xd, k),  sWb[k][lane], acc);
        }
        float mx = acc;
#pragma unroll
        for (int o = 16; o; o >>= 1) mx = fmaxf(mx, __shfl_xor_sync(0xffffffffu, mx, o));
        float e = __expf(acc - mx);
        float ss = e;
#pragma unroll
        for (int o = 16; o; o >>= 1) ss += __shfl_xor_sync(0xffffffffu, ss, o);
        float E = __expf(e / ss);
        Eout[n * HID + lane] = E;
        colacc += E;
    }

    sred[wid][lane] = colacc;
    __syncthreads();
    if (wid == 0) {
        float t = sred[0][lane];
#pragma unroll
        for (int i = 1; i < 8; ++i) t += sred[i][lane];
        atomicAdd(&cs_out[lane], t);
    }
}

// ---------------------------------------------------------------------------
__global__ void __launch_bounds__(256) out_z_kernel(
    const float* __restrict__ E, const float* __restrict__ cs,
    const float* __restrict__ Wout, const float* __restrict__ bout) {
    int lane = threadIdx.x & 31, wid = threadIdx.x >> 5;
    float w = __ldg(&Wout[lane]) / cs[lane];
    float b = __ldg(bout);
    float acc = 0.0f;
    for (int n = blockIdx.x * 8 + wid; n < N_NODES; n += gridDim.x * 8) {
        float v = E[n * HID + lane] * w;
#pragma unroll
        for (int o = 16; o; o >>= 1) v += __shfl_xor_sync(0xffffffffu, v, o);
        float e = __expf(v + b);
        if (lane == 0) { g_zexp[n] = e; acc += e; }
    }
    __shared__ float sred[8];
    if (lane == 0) sred[wid] = acc;
    __syncthreads();
    if (threadIdx.x == 0) {
        float t = 0.0f;
#pragma unroll
        for (int i = 0; i < 8; ++i) t += sred[i];
        atomicAdd(g_S, t);
    }
}

__global__ void out_norm_kernel(float* __restrict__ out) {
    int i = blockIdx.x * blockDim.x + threadIdx.x;
    if (i < N_NODES) out[i] = g_zexp[i] / g_S[0];
}

// ---------------------------------------------------------------------------
extern "C" void kernel_launch(void* const* d_in, const int* in_sizes, int n_in,
                              void* d_out, int out_size) {
    const float* x     = (const float*)d_in[0];
    const void*  ei    = d_in[1];                    // [2, N_EDGES] int32 or int64
    const float* Ain   = (const float*)d_in[2];
    const float* Bin   = (const float*)d_in[3];
    const float* Aconv = (const float*)d_in[4];      // [16,32,32]
    const float* Bconv = (const float*)d_in[5];
    const float* Wout  = (const float*)d_in[6];
    const float* bout  = (const float*)d_in[7];
    float* out         = (float*)d_out;

    float *pA, *pB, *pcs;
    cudaGetSymbolAddress((void**)&pA, g_bufA);
    cudaGetSymbolAddress((void**)&pB, g_bufB);
    cudaGetSymbolAddress((void**)&pcs, g_colsum);

    init_kernel<<<(N_NODES + 255) / 256, 256>>>((const unsigned int*)ei);
    hist_kernel<<<(N_EDGES + 255) / 256, 256>>>(ei);
    scan_kernel<<<1, 1024>>>();
    fill_kernel<<<(N_EDGES + 255) / 256, 256>>>(ei);     // <- profiled slot

    proj_kernel<<<(N_NODES + 7) / 8, 256>>>(x, Ain, Bin, pA);

    float* bi = pA;
    float* bo = pB;
    for (int l = 0; l < NCONV; ++l) {
        conv_kernel<<<888, 256>>>(bi, bo,
                                  Aconv + l * HID * HID, Bconv + l * HID * HID,
                                  pcs + l * HID, pcs + (l + 1) * HID);
        float* t = bi; bi = bo; bo = t;
    }

    out_z_kernel<<<592, 256>>>(bi, pcs + NCONV * HID, Wout, bout);
    out_norm_kernel<<<(N_NODES + 255) / 256, 256>>>(out);
}

// round 5
// speedup vs baseline: 2.2489x; 1.4235x over previous
#include <cuda_runtime.h>

#define N_NODES 100000
#define N_EDGES 3200000
#define HID 32
#define NCONV 16

// ---- device scratch (static globals; no allocation) ----
__device__ int   g_deg[N_NODES];
__device__ int   g_cursor[N_NODES];
__device__ int   g_rowptr[N_NODES + 1];
__device__ float g_invdeg[N_NODES];
__device__ int   g_csr[N_EDGES];
__device__ __align__(16) float g_bufA[N_NODES * HID];
__device__ __align__(16) float g_bufB[N_NODES * HID];
__device__ __align__(16) float g_colsum[(NCONV + 1) * HID];
__device__ float g_zexp[N_NODES];
__device__ float g_S[1];
__device__ int   g_is64;

// ---------------------------------------------------------------------------
// init + dtype detect. If edge_index is int64 (LE), every odd 32-bit word is 0.
__global__ void init_kernel(const unsigned int* __restrict__ raw) {
    int i = blockIdx.x * blockDim.x + threadIdx.x;
    if (i < N_NODES) { g_deg[i] = 0; g_cursor[i] = 0; }
    if (i < (NCONV + 1) * HID) g_colsum[i] = (i < HID) ? 1.0f : 0.0f;
    if (i == 0) g_S[0] = 0.0f;
    if (blockIdx.x == 0) {
        __shared__ int any;
        if (threadIdx.x == 0) any = 0;
        __syncthreads();
        if (threadIdx.x < 64) {
            unsigned v = raw[2 * threadIdx.x + 1 + threadIdx.x * 9973 * 2];
            if (v != 0u) atomicOr(&any, 1);
        }
        __syncthreads();
        if (threadIdx.x == 0) g_is64 = any ? 0 : 1;
    }
}

__device__ __forceinline__ int load_edge(const void* p, long long idx) {
    if (g_is64) return (int)((const long long*)p)[idx];
    return ((const int*)p)[idx];
}

__global__ void hist_kernel(const void* __restrict__ ei) {
    int i = blockIdx.x * blockDim.x + threadIdx.x;
    if (i < N_EDGES) {
        int d = load_edge(ei, (long long)N_EDGES + i);
        if ((unsigned)d < N_NODES) atomicAdd(&g_deg[d], 1);
    }
}

// ---- single-block coalesced scan: g_deg -> g_rowptr (exclusive) + invdeg ----
__global__ void scan_kernel() {
    __shared__ int ws[32];
    __shared__ int s_carry;
    int t = threadIdx.x, lane = t & 31, w = t >> 5;
    if (t == 0) s_carry = 0;
    __syncthreads();
    const int4* deg4 = (const int4*)g_deg;
    const int NI4 = N_NODES / 4;             // 25000 (exact)
    for (int c = 0; c < (NI4 + 1023) / 1024; ++c) {
        int i4 = c * 1024 + t;
        int4 d = (i4 < NI4) ? deg4[i4] : make_int4(0, 0, 0, 0);
        int tsum = d.x + d.y + d.z + d.w;
        int v = tsum;
#pragma unroll
        for (int o = 1; o < 32; o <<= 1) {
            int u = __shfl_up_sync(0xffffffffu, v, o);
            if (lane >= o) v += u;
        }
        if (lane == 31) ws[w] = v;
        __syncthreads();
        if (w == 0) {
            int s = ws[lane];
#pragma unroll
            for (int o = 1; o < 32; o <<= 1) {
                int u = __shfl_up_sync(0xffffffffu, s, o);
                if (lane >= o) s += u;
            }
            ws[lane] = s;
        }
        __syncthreads();
        int excl = s_carry + (w ? ws[w - 1] : 0) + v - tsum;
        if (i4 < NI4) {
            int base = i4 * 4;
            int4 rp;
            rp.x = excl; rp.y = excl + d.x; rp.z = rp.y + d.y; rp.w = rp.z + d.z;
            *(int4*)&g_rowptr[base] = rp;
            float4 iv;
            iv.x = 1.0f / (float)max(d.x, 1);
            iv.y = 1.0f / (float)max(d.y, 1);
            iv.z = 1.0f / (float)max(d.z, 1);
            iv.w = 1.0f / (float)max(d.w, 1);
            *(float4*)&g_invdeg[base] = iv;
        }
        __syncthreads();
        if (t == 0) s_carry += ws[31];
        __syncthreads();
    }
    if (t == 0) g_rowptr[N_NODES] = s_carry;
}

__global__ void fill_kernel(const void* __restrict__ ei) {
    int i = blockIdx.x * blockDim.x + threadIdx.x;
    if (i < N_EDGES) {
        int s = load_edge(ei, i);
        int d = load_edge(ei, (long long)N_EDGES + i);
        if ((unsigned)d >= N_NODES || (unsigned)s >= N_NODES) return;
        int p = atomicAdd(&g_cursor[d], 1);
        g_csr[g_rowptr[d] + p] = s;
    }
}

// ---------------------------------------------------------------------------
// proj_in: x[N,4] -> inner-softmax(avg@A_in + x@B_in) [N,32]. One warp/node.
__global__ void __launch_bounds__(256) proj_kernel(
    const float* __restrict__ x, const float* __restrict__ Ain,
    const float* __restrict__ Bin, float* __restrict__ out) {
    int lane = threadIdx.x & 31, wid = threadIdx.x >> 5;
    int n = blockIdx.x * 8 + wid;
    if (n >= N_NODES) return;
    int beg = g_rowptr[n], end = g_rowptr[n + 1];
    int gb = lane >> 2, ft = lane & 3;
    float sum = 0.0f;
    for (int base = beg; base < end; base += 8) {
        int j = base + gb;
        if (j < end) {
            int s = __ldg(&g_csr[j]);
            sum += __ldg(&x[s * 4 + ft]);
        }
    }
    sum += __shfl_xor_sync(0xffffffffu, sum, 4);
    sum += __shfl_xor_sync(0xffffffffu, sum, 8);
    sum += __shfl_xor_sync(0xffffffffu, sum, 16);
    float invd = g_invdeg[n];
    float a0 = __shfl_sync(0xffffffffu, sum, 0) * invd;
    float a1 = __shfl_sync(0xffffffffu, sum, 1) * invd;
    float a2 = __shfl_sync(0xffffffffu, sum, 2) * invd;
    float a3 = __shfl_sync(0xffffffffu, sum, 3) * invd;
    float4 xv = *(const float4*)&x[n * 4];
    float acc = a0 * __ldg(&Ain[lane])      + a1 * __ldg(&Ain[32 + lane])
              + a2 * __ldg(&Ain[64 + lane]) + a3 * __ldg(&Ain[96 + lane])
              + xv.x * __ldg(&Bin[lane])      + xv.y * __ldg(&Bin[32 + lane])
              + xv.z * __ldg(&Bin[64 + lane]) + xv.w * __ldg(&Bin[96 + lane]);
    float mx = acc;
#pragma unroll
    for (int o = 16; o; o >>= 1) mx = fmaxf(mx, __shfl_xor_sync(0xffffffffu, mx, o));
    float e = __expf(acc - mx);
    float ss = e;
#pragma unroll
    for (int o = 16; o; o >>= 1) ss += __shfl_xor_sync(0xffffffffu, ss, o);
    out[n * HID + lane] = e / ss;
}

// ---------------------------------------------------------------------------
// hidden conv layer, float4-vectorized: 8 lanes per node (4 features/lane),
// 4 nodes per warp. Gathers are LDG.128 (full 128B row per 8-lane group, 4
// rows per warp instruction). Matvec broadcasts avg/xd 4 k's at a time and
// reads weight rows as LDS.128 (broadcast across groups). ~3x fewer
// LSU/MIO/shfl instructions than the scalar version.
__global__ void __launch_bounds__(256) conv_kernel(
    const float* __restrict__ Ein, float* __restrict__ Eout,
    const float* __restrict__ Wa, const float* __restrict__ Wb,
    const float* __restrict__ cs_in, float* __restrict__ cs_out) {
    __shared__ __align__(16) float sWa[HID][HID];
    __shared__ __align__(16) float sWb[HID][HID];
    __shared__ __align__(16) float sred[8][HID];
    int tid = threadIdx.x;
    int lane = tid & 31, wid = tid >> 5;
    for (int i = tid; i < HID * HID; i += 256) {
        ((float*)sWa)[i] = __ldg(&Wa[i]);
        ((float*)sWb)[i] = __ldg(&Wb[i]);
    }
    __syncthreads();

    int g8 = lane & 24;          // group base lane (g*8)
    int fl = lane & 7;           // lane within group
    const float4* E4in = (const float4*)Ein;

    float4 cs4 = *(const float4*)&cs_in[fl * 4];
    float4 invS4 = make_float4(1.0f / cs4.x, 1.0f / cs4.y, 1.0f / cs4.z, 1.0f / cs4.w);
    float4 colacc = make_float4(0.f, 0.f, 0.f, 0.f);

    const int NQ = (N_NODES + 3) / 4;        // 25000
    for (int q = blockIdx.x * 8 + wid; q < NQ; q += gridDim.x * 8) {
        int n = q * 4 + (lane >> 3);
        bool valid = (n < N_NODES);
        int beg = valid ? g_rowptr[n] : 0;
        int end = valid ? g_rowptr[n + 1] : 0;
        int deg = end - beg;
        int md = deg;
        md = max(md, __shfl_xor_sync(0xffffffffu, md, 8));
        md = max(md, __shfl_xor_sync(0xffffffffu, md, 16));

        float4 sum = make_float4(0.f, 0.f, 0.f, 0.f);
        int idxreg = 0;
        for (int j = 0; j < md; ++j) {
            if ((j & 7) == 0) {
                int p = beg + j + fl;
                idxreg = (p < end) ? __ldg(&g_csr[p]) : 0;
            }
            int s = __shfl_sync(0xffffffffu, idxreg, g8 + (j & 7));
            if (j < deg) {
                float4 v = __ldg(&E4in[s * 8 + fl]);
                sum.x += v.x; sum.y += v.y; sum.z += v.z; sum.w += v.w;
            }
        }

        float sc = valid ? g_invdeg[n] : 0.0f;
        float4 avg = make_float4(sum.x * sc * invS4.x, sum.y * sc * invS4.y,
                                 sum.z * sc * invS4.z, sum.w * sc * invS4.w);
        float4 xd = make_float4(0.f, 0.f, 0.f, 0.f);
        if (valid) xd = __ldg(&E4in[n * 8 + fl]);
        xd.x *= invS4.x; xd.y *= invS4.y; xd.z *= invS4.z; xd.w *= invS4.w;

        float4 acc = make_float4(0.f, 0.f, 0.f, 0.f);
#pragma unroll
        for (int kb = 0; kb < HID; kb += 4) {
            int src = g8 + (kb >> 2);
            float a0 = __shfl_sync(0xffffffffu, avg.x, src);
            float a1 = __shfl_sync(0xffffffffu, avg.y, src);
            float a2 = __shfl_sync(0xffffffffu, avg.z, src);
            float a3 = __shfl_sync(0xffffffffu, avg.w, src);
            float x0 = __shfl_sync(0xffffffffu, xd.x, src);
            float x1 = __shfl_sync(0xffffffffu, xd.y, src);
            float x2 = __shfl_sync(0xffffffffu, xd.z, src);
            float x3 = __shfl_sync(0xffffffffu, xd.w, src);
            float4 w;
            w = *(const float4*)&sWa[kb + 0][fl * 4];
            acc.x = fmaf(a0, w.x, acc.x); acc.y = fmaf(a0, w.y, acc.y);
            acc.z = fmaf(a0, w.z, acc.z); acc.w = fmaf(a0, w.w, acc.w);
            w = *(const float4*)&sWa[kb + 1][fl * 4];
            acc.x = fmaf(a1, w.x, acc.x); acc.y = fmaf(a1, w.y, acc.y);
            acc.z = fmaf(a1, w.z, acc.z); acc.w = fmaf(a1, w.w, acc.w);
            w = *(const float4*)&sWa[kb + 2][fl * 4];
            acc.x = fmaf(a2, w.x, acc.x); acc.y = fmaf(a2, w.y, acc.y);
            acc.z = fmaf(a2, w.z, acc.z); acc.w = fmaf(a2, w.w, acc.w);
            w = *(const float4*)&sWa[kb + 3][fl * 4];
            acc.x = fmaf(a3, w.x, acc.x); acc.y = fmaf(a3, w.y, acc.y);
            acc.z = fmaf(a3, w.z, acc.z); acc.w = fmaf(a3, w.w, acc.w);
            w = *(const float4*)&sWb[kb + 0][fl * 4];
            acc.x = fmaf(x0, w.x, acc.x); acc.y = fmaf(x0, w.y, acc.y);
            acc.z = fmaf(x0, w.z, acc.z); acc.w = fmaf(x0, w.w, acc.w);
            w = *(const float4*)&sWb[kb + 1][fl * 4];
            acc.x = fmaf(x1, w.x, acc.x); acc.y = fmaf(x1, w.y, acc.y);
            acc.z = fmaf(x1, w.z, acc.z); acc.w = fmaf(x1, w.w, acc.w);
            w = *(const float4*)&sWb[kb + 2][fl * 4];
            acc.x = fmaf(x2, w.x, acc.x); acc.y = fmaf(x2, w.y, acc.y);
            acc.z = fmaf(x2, w.z, acc.z); acc.w = fmaf(x2, w.w, acc.w);
            w = *(const float4*)&sWb[kb + 3][fl * 4];
            acc.x = fmaf(x3, w.x, acc.x); acc.y = fmaf(x3, w.y, acc.y);
            acc.z = fmaf(x3, w.z, acc.z); acc.w = fmaf(x3, w.w, acc.w);
        }

        // inner softmax over the node's 32 features (8 lanes x 4 comps)
        float mx = fmaxf(fmaxf(acc.x, acc.y), fmaxf(acc.z, acc.w));
        mx = fmaxf(mx, __shfl_xor_sync(0xffffffffu, mx, 1));
        mx = fmaxf(mx, __shfl_xor_sync(0xffffffffu, mx, 2));
        mx = fmaxf(mx, __shfl_xor_sync(0xffffffffu, mx, 4));
        float4 e = make_float4(__expf(acc.x - mx), __expf(acc.y - mx),
                               __expf(acc.z - mx), __expf(acc.w - mx));
        float ss = (e.x + e.y) + (e.z + e.w);
        ss += __shfl_xor_sync(0xffffffffu, ss, 1);
        ss += __shfl_xor_sync(0xffffffffu, ss, 2);
        ss += __shfl_xor_sync(0xffffffffu, ss, 4);
        float r = 1.0f / ss;
        float4 E = make_float4(__expf(e.x * r), __expf(e.y * r),
                               __expf(e.z * r), __expf(e.w * r));
        if (valid) {
            *(float4*)&Eout[n * HID + fl * 4] = E;
            colacc.x += E.x; colacc.y += E.y; colacc.z += E.z; colacc.w += E.w;
        }
    }

    // reduce colacc across the 4 groups (lanes sharing fl)
#pragma unroll
    for (int o = 8; o <= 16; o <<= 1) {
        colacc.x += __shfl_xor_sync(0xffffffffu, colacc.x, o);
        colacc.y += __shfl_xor_sync(0xffffffffu, colacc.y, o);
        colacc.z += __shfl_xor_sync(0xffffffffu, colacc.z, o);
        colacc.w += __shfl_xor_sync(0xffffffffu, colacc.w, o);
    }
    if (lane < 8) *(float4*)&sred[wid][lane * 4] = colacc;
    __syncthreads();
    if (wid == 0) {
        float t = sred[0][lane];
#pragma unroll
        for (int i = 1; i < 8; ++i) t += sred[i][lane];
        atomicAdd(&cs_out[lane], t);
    }
}

// ---------------------------------------------------------------------------
__global__ void __launch_bounds__(256) out_z_kernel(
    const float* __restrict__ E, const float* __restrict__ cs,
    const float* __restrict__ Wout, const float* __restrict__ bout) {
    int lane = threadIdx.x & 31, wid = threadIdx.x >> 5;
    float w = __ldg(&Wout[lane]) / cs[lane];
    float b = __ldg(bout);
    float acc = 0.0f;
    for (int n = blockIdx.x * 8 + wid; n < N_NODES; n += gridDim.x * 8) {
        float v = E[n * HID + lane] * w;
#pragma unroll
        for (int o = 16; o; o >>= 1) v += __shfl_xor_sync(0xffffffffu, v, o);
        float e = __expf(v + b);
        if (lane == 0) { g_zexp[n] = e; acc += e; }
    }
    __shared__ float sred[8];
    if (lane == 0) sred[wid] = acc;
    __syncthreads();
    if (threadIdx.x == 0) {
        float t = 0.0f;
#pragma unroll
        for (int i = 0; i < 8; ++i) t += sred[i];
        atomicAdd(g_S, t);
    }
}

__global__ void out_norm_kernel(float* __restrict__ out) {
    int i = blockIdx.x * blockDim.x + threadIdx.x;
    if (i < N_NODES) out[i] = g_zexp[i] / g_S[0];
}

// ---------------------------------------------------------------------------
extern "C" void kernel_launch(void* const* d_in, const int* in_sizes, int n_in,
                              void* d_out, int out_size) {
    const float* x     = (const float*)d_in[0];
    const void*  ei    = d_in[1];                    // [2, N_EDGES] int32 or int64
    const float* Ain   = (const float*)d_in[2];
    const float* Bin   = (const float*)d_in[3];
    const float* Aconv = (const float*)d_in[4];      // [16,32,32]
    const float* Bconv = (const float*)d_in[5];
    const float* Wout  = (const float*)d_in[6];
    const float* bout  = (const float*)d_in[7];
    float* out         = (float*)d_out;

    float *pA, *pB, *pcs;
    cudaGetSymbolAddress((void**)&pA, g_bufA);
    cudaGetSymbolAddress((void**)&pB, g_bufB);
    cudaGetSymbolAddress((void**)&pcs, g_colsum);

    init_kernel<<<(N_NODES + 255) / 256, 256>>>((const unsigned int*)ei);
    hist_kernel<<<(N_EDGES + 255) / 256, 256>>>(ei);
    scan_kernel<<<1, 1024>>>();
    fill_kernel<<<(N_EDGES + 255) / 256, 256>>>(ei);

    proj_kernel<<<(N_NODES + 7) / 8, 256>>>(x, Ain, Bin, pA);

    float* bi = pA;
    float* bo = pB;
    for (int l = 0; l < NCONV; ++l) {
        conv_kernel<<<888, 256>>>(bi, bo,
                                  Aconv + l * HID * HID, Bconv + l * HID * HID,
                                  pcs + l * HID, pcs + (l + 1) * HID);
        float* t = bi; bi = bo; bo = t;
    }

    out_z_kernel<<<592, 256>>>(bi, pcs + NCONV * HID, Wout, bout);
    out_norm_kernel<<<(N_NODES + 255) / 256, 256>>>(out);
}

// round 6
// speedup vs baseline: 2.6748x; 1.1893x over previous
#include <cuda_runtime.h>
#include <cuda_fp16.h>

#define N_NODES 100000
#define N_EDGES 3200000
#define HID 32
#define NCONV 16
#define NGRP (N_NODES / 8)        // 12500 node-groups (8 nodes/warp)

// ---- device scratch (static globals; zero-initialized at load) ----
__device__ int   g_deg[N_NODES];
__device__ int   g_cursor[N_NODES];
__device__ int   g_rowptr[N_NODES + 1];
__device__ float g_invdeg[N_NODES];
__device__ int   g_csr[N_EDGES];
__device__ __align__(16) __half g_hbufA[N_NODES * HID];
__device__ __align__(16) __half g_hbufB[N_NODES * HID];
__device__ __align__(16) float  g_colsum[(NCONV + 1) * HID];
__device__ float g_zexp[N_NODES];
__device__ float g_S[1];

// ---------------------------------------------------------------------------
// per-block dtype detect: if edge_index is int64 (LE), odd 32-bit words are 0.
__device__ __forceinline__ bool detect_is64(const void* ei) {
    __shared__ int s_any;
    if (threadIdx.x == 0) s_any = 0;
    __syncthreads();
    unsigned e = (threadIdx.x * 9973u + blockIdx.x * 131u) % N_EDGES;
    unsigned w = ((const unsigned*)ei)[2 * (size_t)e + 1];
    if (w != 0u) atomicOr(&s_any, 1);
    __syncthreads();
    return s_any == 0;
}

__device__ __forceinline__ int load_edge(const void* p, long long idx, bool is64) {
    if (is64) return (int)((const long long*)p)[idx];
    return ((const int*)p)[idx];
}

// histogram of dst (g_deg starts zero: static init on call 1, scan re-zeroes after)
__global__ void hist_kernel(const void* __restrict__ ei) {
    bool is64 = detect_is64(ei);
    int i = blockIdx.x * blockDim.x + threadIdx.x;
    if (i < N_EDGES) {
        int d = load_edge(ei, (long long)N_EDGES + i, is64);
        if ((unsigned)d < N_NODES) atomicAdd(&g_deg[d], 1);
    }
}

// single-block scan: deg -> rowptr (exclusive) + invdeg.
// Also: re-zero deg & cursor (for next replay / this call's fill), init colsum/S.
__global__ void scan_kernel() {
    __shared__ int ws[32];
    __shared__ int s_carry;
    int t = threadIdx.x, lane = t & 31, w = t >> 5;
    if (t == 0) s_carry = 0;
    if (t < (NCONV + 1) * HID) g_colsum[t] = (t < HID) ? 1.0f : 0.0f;
    if (t == 0) g_S[0] = 0.0f;
    __syncthreads();
    int4* deg4 = (int4*)g_deg;
    int4* cur4 = (int4*)g_cursor;
    const int NI4 = N_NODES / 4;             // 25000 (exact)
    for (int c = 0; c < (NI4 + 1023) / 1024; ++c) {
        int i4 = c * 1024 + t;
        int4 d = (i4 < NI4) ? deg4[i4] : make_int4(0, 0, 0, 0);
        int tsum = d.x + d.y + d.z + d.w;
        int v = tsum;
#pragma unroll
        for (int o = 1; o < 32; o <<= 1) {
            int u = __shfl_up_sync(0xffffffffu, v, o);
            if (lane >= o) v += u;
        }
        if (lane == 31) ws[w] = v;
        __syncthreads();
        if (w == 0) {
            int s = ws[lane];
#pragma unroll
            for (int o = 1; o < 32; o <<= 1) {
                int u = __shfl_up_sync(0xffffffffu, s, o);
                if (lane >= o) s += u;
            }
            ws[lane] = s;
        }
        __syncthreads();
        int excl = s_carry + (w ? ws[w - 1] : 0) + v - tsum;
        if (i4 < NI4) {
            int base = i4 * 4;
            int4 rp;
            rp.x = excl; rp.y = excl + d.x; rp.z = rp.y + d.y; rp.w = rp.z + d.z;
            *(int4*)&g_rowptr[base] = rp;
            float4 iv;
            iv.x = 1.0f / (float)max(d.x, 1);
            iv.y = 1.0f / (float)max(d.y, 1);
            iv.z = 1.0f / (float)max(d.z, 1);
            iv.w = 1.0f / (float)max(d.w, 1);
            *(float4*)&g_invdeg[base] = iv;
            deg4[i4] = make_int4(0, 0, 0, 0);   // reset for next call
            cur4[i4] = make_int4(0, 0, 0, 0);   // reset for fill
        }
        __syncthreads();
        if (t == 0) s_carry += ws[31];
        __syncthreads();
    }
    if (t == 0) g_rowptr[N_NODES] = s_carry;
}

__global__ void fill_kernel(const void* __restrict__ ei) {
    bool is64 = detect_is64(ei);
    int i = blockIdx.x * blockDim.x + threadIdx.x;
    if (i < N_EDGES) {
        int s = load_edge(ei, i, is64);
        int d = load_edge(ei, (long long)N_EDGES + i, is64);
        if ((unsigned)d >= N_NODES || (unsigned)s >= N_NODES) return;
        int p = atomicAdd(&g_cursor[d], 1);
        g_csr[g_rowptr[d] + p] = s;
    }
}

// ---------------------------------------------------------------------------
// proj_in: x[N,4] -> inner-softmax(avg@A_in + x@B_in) [N,32] as fp16.
__global__ void __launch_bounds__(256) proj_kernel(
    const float* __restrict__ x, const float* __restrict__ Ain,
    const float* __restrict__ Bin, __half* __restrict__ out) {
    int lane = threadIdx.x & 31, wid = threadIdx.x >> 5;
    int n = blockIdx.x * 8 + wid;
    if (n >= N_NODES) return;
    int beg = g_rowptr[n], end = g_rowptr[n + 1];
    int gb = lane >> 2, ft = lane & 3;
    float sum = 0.0f;
    for (int base = beg; base < end; base += 8) {
        int j = base + gb;
        if (j < end) {
            int s = __ldg(&g_csr[j]);
            sum += __ldg(&x[s * 4 + ft]);
        }
    }
    sum += __shfl_xor_sync(0xffffffffu, sum, 4);
    sum += __shfl_xor_sync(0xffffffffu, sum, 8);
    sum += __shfl_xor_sync(0xffffffffu, sum, 16);
    float invd = g_invdeg[n];
    float a0 = __shfl_sync(0xffffffffu, sum, 0) * invd;
    float a1 = __shfl_sync(0xffffffffu, sum, 1) * invd;
    float a2 = __shfl_sync(0xffffffffu, sum, 2) * invd;
    float a3 = __shfl_sync(0xffffffffu, sum, 3) * invd;
    float4 xv = *(const float4*)&x[n * 4];
    float acc = a0 * __ldg(&Ain[lane])      + a1 * __ldg(&Ain[32 + lane])
              + a2 * __ldg(&Ain[64 + lane]) + a3 * __ldg(&Ain[96 + lane])
              + xv.x * __ldg(&Bin[lane])      + xv.y * __ldg(&Bin[32 + lane])
              + xv.z * __ldg(&Bin[64 + lane]) + xv.w * __ldg(&Bin[96 + lane]);
    float mx = acc;
#pragma unroll
    for (int o = 16; o; o >>= 1) mx = fmaxf(mx, __shfl_xor_sync(0xffffffffu, mx, o));
    float e = __expf(acc - mx);
    float ss = e;
#pragma unroll
    for (int o = 16; o; o >>= 1) ss += __shfl_xor_sync(0xffffffffu, ss, o);
    out[n * HID + lane] = __float2half_rn(e / ss);
}

// ---------------------------------------------------------------------------
// hidden conv layer, fp16 storage: 8 nodes/warp, 4 lanes/node, 8 feats/lane.
// Gather = LDG.128 of 8 halves -> fp32 accumulate. Matvec/softmax in fp32.
__global__ void __launch_bounds__(256) conv_kernel(
    const __half* __restrict__ Ein, __half* __restrict__ Eout,
    const float* __restrict__ Wa, const float* __restrict__ Wb,
    const float* __restrict__ cs_in, float* __restrict__ cs_out) {
    __shared__ __align__(16) float sWa[HID][HID];
    __shared__ __align__(16) float sWb[HID][HID];
    __shared__ __align__(16) float sred[8][HID];
    int tid = threadIdx.x;
    int lane = tid & 31, wid = tid >> 5;
    for (int i = tid; i < HID * HID; i += 256) {
        ((float*)sWa)[i] = __ldg(&Wa[i]);
        ((float*)sWb)[i] = __ldg(&Wb[i]);
    }
    __syncthreads();

    int nid = lane >> 2;         // node within warp (0..7)
    int fl  = lane & 3;          // quarter-row: features fl*8 .. fl*8+7
    int nb  = lane & 28;         // node base lane

    float invS[8];
#pragma unroll
    for (int i = 0; i < 8; ++i) invS[i] = 1.0f / cs_in[fl * 8 + i];
    float colacc[8];
#pragma unroll
    for (int i = 0; i < 8; ++i) colacc[i] = 0.0f;

    int q = blockIdx.x * 8 + wid;
    if (q < NGRP) {
        int n = q * 8 + nid;     // always < N_NODES (NGRP*8 == N_NODES)
        int beg = g_rowptr[n], end = g_rowptr[n + 1];
        int deg = end - beg;
        int md = deg;
        md = max(md, __shfl_xor_sync(0xffffffffu, md, 4));
        md = max(md, __shfl_xor_sync(0xffffffffu, md, 8));
        md = max(md, __shfl_xor_sync(0xffffffffu, md, 16));

        float sum[8];
#pragma unroll
        for (int i = 0; i < 8; ++i) sum[i] = 0.0f;

        const uint4* E4 = (const uint4*)Ein;
        int idxreg = 0;
        for (int j = 0; j < md; ++j) {
            if ((j & 3) == 0) {
                int p = beg + j + fl;
                idxreg = (p < end) ? __ldg(&g_csr[p]) : 0;
            }
            int s = __shfl_sync(0xffffffffu, idxreg, nb + (j & 3));
            if (j < deg) {
                uint4 v = __ldg(&E4[s * 4 + fl]);
                float2 f0 = __half22float2(*(__half2*)&v.x);
                float2 f1 = __half22float2(*(__half2*)&v.y);
                float2 f2 = __half22float2(*(__half2*)&v.z);
                float2 f3 = __half22float2(*(__half2*)&v.w);
                sum[0] += f0.x; sum[1] += f0.y; sum[2] += f1.x; sum[3] += f1.y;
                sum[4] += f2.x; sum[5] += f2.y; sum[6] += f3.x; sum[7] += f3.y;
            }
        }

        float sc = g_invdeg[n];
        uint4 vx = __ldg(&E4[n * 4 + fl]);
        float2 x0 = __half22float2(*(__half2*)&vx.x);
        float2 x1 = __half22float2(*(__half2*)&vx.y);
        float2 x2 = __half22float2(*(__half2*)&vx.z);
        float2 x3 = __half22float2(*(__half2*)&vx.w);
        float avg[8], xd[8];
        xd[0] = x0.x; xd[1] = x0.y; xd[2] = x1.x; xd[3] = x1.y;
        xd[4] = x2.x; xd[5] = x2.y; xd[6] = x3.x; xd[7] = x3.y;
#pragma unroll
        for (int i = 0; i < 8; ++i) {
            avg[i] = sum[i] * sc * invS[i];
            xd[i] *= invS[i];
        }

        float acc[8];
#pragma unroll
        for (int i = 0; i < 8; ++i) acc[i] = 0.0f;
#pragma unroll
        for (int c = 0; c < 4; ++c) {
            int src = nb + c;
#pragma unroll
            for (int j = 0; j < 8; ++j) {
                float a  = __shfl_sync(0xffffffffu, avg[j], src);
                float xv = __shfl_sync(0xffffffffu, xd[j],  src);
                int k = c * 8 + j;
                float4 wa0 = *(const float4*)&sWa[k][fl * 8];
                float4 wa1 = *(const float4*)&sWa[k][fl * 8 + 4];
                float4 wb0 = *(const float4*)&sWb[k][fl * 8];
                float4 wb1 = *(const float4*)&sWb[k][fl * 8 + 4];
                acc[0] = fmaf(a, wa0.x, acc[0]); acc[1] = fmaf(a, wa0.y, acc[1]);
                acc[2] = fmaf(a, wa0.z, acc[2]); acc[3] = fmaf(a, wa0.w, acc[3]);
                acc[4] = fmaf(a, wa1.x, acc[4]); acc[5] = fmaf(a, wa1.y, acc[5]);
                acc[6] = fmaf(a, wa1.z, acc[6]); acc[7] = fmaf(a, wa1.w, acc[7]);
                acc[0] = fmaf(xv, wb0.x, acc[0]); acc[1] = fmaf(xv, wb0.y, acc[1]);
                acc[2] = fmaf(xv, wb0.z, acc[2]); acc[3] = fmaf(xv, wb0.w, acc[3]);
                acc[4] = fmaf(xv, wb1.x, acc[4]); acc[5] = fmaf(xv, wb1.y, acc[5]);
                acc[6] = fmaf(xv, wb1.z, acc[6]); acc[7] = fmaf(xv, wb1.w, acc[7]);
            }
        }

        // inner softmax over node's 32 features (4 lanes x 8 comps)
        float mx = acc[0];
#pragma unroll
        for (int i = 1; i < 8; ++i) mx = fmaxf(mx, acc[i]);
        mx = fmaxf(mx, __shfl_xor_sync(0xffffffffu, mx, 1));
        mx = fmaxf(mx, __shfl_xor_sync(0xffffffffu, mx, 2));
        float e[8], ss = 0.0f;
#pragma unroll
        for (int i = 0; i < 8; ++i) { e[i] = __expf(acc[i] - mx); ss += e[i]; }
        ss += __shfl_xor_sync(0xffffffffu, ss, 1);
        ss += __shfl_xor_sync(0xffffffffu, ss, 2);
        float r = 1.0f / ss;
        float E[8];
#pragma unroll
        for (int i = 0; i < 8; ++i) {
            E[i] = __expf(e[i] * r);
            colacc[i] += E[i];
        }
        uint4 o;
        *(__half2*)&o.x = __floats2half2_rn(E[0], E[1]);
        *(__half2*)&o.y = __floats2half2_rn(E[2], E[3]);
        *(__half2*)&o.z = __floats2half2_rn(E[4], E[5]);
        *(__half2*)&o.w = __floats2half2_rn(E[6], E[7]);
        ((uint4*)Eout)[n * 4 + fl] = o;
    }

    // column-sum reduction: sum across the 8 nodes (lanes with same fl)
#pragma unroll
    for (int o = 4; o <= 16; o <<= 1) {
#pragma unroll
        for (int i = 0; i < 8; ++i)
            colacc[i] += __shfl_xor_sync(0xffffffffu, colacc[i], o);
    }
    if (lane < 4) {
        float4 c0 = make_float4(colacc[0], colacc[1], colacc[2], colacc[3]);
        float4 c1 = make_float4(colacc[4], colacc[5], colacc[6], colacc[7]);
        *(float4*)&sred[wid][fl * 8]     = c0;
        *(float4*)&sred[wid][fl * 8 + 4] = c1;
    }
    __syncthreads();
    if (wid == 0) {
        float t = sred[0][lane];
#pragma unroll
        for (int i = 1; i < 8; ++i) t += sred[i][lane];
        atomicAdd(&cs_out[lane], t);
    }
}

// ---------------------------------------------------------------------------
__global__ void __launch_bounds__(256) out_z_kernel(
    const __half* __restrict__ E, const float* __restrict__ cs,
    const float* __restrict__ Wout, const float* __restrict__ bout) {
    int lane = threadIdx.x & 31, wid = threadIdx.x >> 5;
    float w = __ldg(&Wout[lane]) / cs[lane];
    float b = __ldg(bout);
    float acc = 0.0f;
    for (int n = blockIdx.x * 8 + wid; n < N_NODES; n += gridDim.x * 8) {
        float v = __half2float(E[n * HID + lane]) * w;
#pragma unroll
        for (int o = 16; o; o >>= 1) v += __shfl_xor_sync(0xffffffffu, v, o);
        float e = __expf(v + b);
        if (lane == 0) { g_zexp[n] = e; acc += e; }
    }
    __shared__ float sred[8];
    if (lane == 0) sred[wid] = acc;
    __syncthreads();
    if (threadIdx.x == 0) {
        float t = 0.0f;
#pragma unroll
        for (int i = 0; i < 8; ++i) t += sred[i];
        atomicAdd(g_S, t);
    }
}

__global__ void out_norm_kernel(float* __restrict__ out) {
    int i = blockIdx.x * blockDim.x + threadIdx.x;
    if (i < N_NODES) out[i] = g_zexp[i] / g_S[0];
}

// ---------------------------------------------------------------------------
extern "C" void kernel_launch(void* const* d_in, const int* in_sizes, int n_in,
                              void* d_out, int out_size) {
    const float* x     = (const float*)d_in[0];
    const void*  ei    = d_in[1];                    // [2, N_EDGES] int32 or int64
    const float* Ain   = (const float*)d_in[2];
    const float* Bin   = (const float*)d_in[3];
    const float* Aconv = (const float*)d_in[4];      // [16,32,32]
    const float* Bconv = (const float*)d_in[5];
    const float* Wout  = (const float*)d_in[6];
    const float* bout  = (const float*)d_in[7];
    float* out         = (float*)d_out;

    __half *pA, *pB;
    float *pcs;
    cudaGetSymbolAddress((void**)&pA, g_hbufA);
    cudaGetSymbolAddress((void**)&pB, g_hbufB);
    cudaGetSymbolAddress((void**)&pcs, g_colsum);

    hist_kernel<<<(N_EDGES + 255) / 256, 256>>>(ei);
    scan_kernel<<<1, 1024>>>();
    fill_kernel<<<(N_EDGES + 255) / 256, 256>>>(ei);

    proj_kernel<<<(N_NODES + 7) / 8, 256>>>(x, Ain, Bin, pA);   // profiled slot

    __half* bi = pA;
    __half* bo = pB;
    for (int l = 0; l < NCONV; ++l) {
        conv_kernel<<<(NGRP + 7) / 8, 256>>>(bi, bo,
                                  Aconv + l * HID * HID, Bconv + l * HID * HID,
                                  pcs + l * HID, pcs + (l + 1) * HID);
        __half* t = bi; bi = bo; bo = t;
    }

    out_z_kernel<<<592, 256>>>(bi, pcs + NCONV * HID, Wout, bout);
    out_norm_kernel<<<(N_NODES + 255) / 256, 256>>>(out);
}

// round 7
// speedup vs baseline: 2.6851x; 1.0039x over previous
#include <cuda_runtime.h>
#include <cuda_fp16.h>

#define N_NODES 100000
#define N_EDGES 3200000
#define HID 32
#define NCONV 16
#define NGRP (N_NODES / 8)        // 12500 node-groups (8 nodes/warp)

// ---- device scratch (static globals; zero-initialized at load) ----
__device__ int   g_deg[N_NODES];
__device__ int   g_cursor[N_NODES];
__device__ int   g_rowptr[N_NODES + 1];
__device__ float g_invdeg[N_NODES];
__device__ int   g_csr[N_EDGES];
__device__ __align__(16) __half g_hbufA[N_NODES * HID];
__device__ __align__(16) __half g_hbufB[N_NODES * HID];
__device__ __align__(16) float  g_colsum[(NCONV + 1) * HID];
__device__ float g_zexp[N_NODES];
__device__ float g_S[1];
__device__ int   g_bhist[128];
__device__ int   g_bstart[128];
__device__ int   g_bcur[128];
__device__ int   g_perm[N_NODES];

// ---------------------------------------------------------------------------
// per-block dtype detect: if edge_index is int64 (LE), odd 32-bit words are 0.
__device__ __forceinline__ bool detect_is64(const void* ei) {
    __shared__ int s_any;
    if (threadIdx.x == 0) s_any = 0;
    __syncthreads();
    unsigned e = (threadIdx.x * 9973u + blockIdx.x * 131u) % N_EDGES;
    unsigned w = ((const unsigned*)ei)[2 * (size_t)e + 1];
    if (w != 0u) atomicOr(&s_any, 1);
    __syncthreads();
    return s_any == 0;
}

__device__ __forceinline__ int load_edge(const void* p, long long idx, bool is64) {
    if (is64) return (int)((const long long*)p)[idx];
    return ((const int*)p)[idx];
}

// histogram of dst (g_deg starts zero: static init on call 1, scan re-zeroes after)
__global__ void hist_kernel(const void* __restrict__ ei) {
    bool is64 = detect_is64(ei);
    int i = blockIdx.x * blockDim.x + threadIdx.x;
    if (i < N_EDGES) {
        int d = load_edge(ei, (long long)N_EDGES + i, is64);
        if ((unsigned)d < N_NODES) atomicAdd(&g_deg[d], 1);
    }
}

// single-block scan: deg -> rowptr (exclusive) + invdeg.
// Also: re-zero deg & cursor, init colsum/S, zero bucket histogram.
__global__ void scan_kernel() {
    __shared__ int ws[32];
    __shared__ int s_carry;
    int t = threadIdx.x, lane = t & 31, w = t >> 5;
    if (t == 0) s_carry = 0;
    if (t < (NCONV + 1) * HID) g_colsum[t] = (t < HID) ? 1.0f : 0.0f;
    if (t == 0) g_S[0] = 0.0f;
    if (t < 128) g_bhist[t] = 0;
    __syncthreads();
    int4* deg4 = (int4*)g_deg;
    int4* cur4 = (int4*)g_cursor;
    const int NI4 = N_NODES / 4;             // 25000 (exact)
    for (int c = 0; c < (NI4 + 1023) / 1024; ++c) {
        int i4 = c * 1024 + t;
        int4 d = (i4 < NI4) ? deg4[i4] : make_int4(0, 0, 0, 0);
        int tsum = d.x + d.y + d.z + d.w;
        int v = tsum;
#pragma unroll
        for (int o = 1; o < 32; o <<= 1) {
            int u = __shfl_up_sync(0xffffffffu, v, o);
            if (lane >= o) v += u;
        }
        if (lane == 31) ws[w] = v;
        __syncthreads();
        if (w == 0) {
            int s = ws[lane];
#pragma unroll
            for (int o = 1; o < 32; o <<= 1) {
                int u = __shfl_up_sync(0xffffffffu, s, o);
                if (lane >= o) s += u;
            }
            ws[lane] = s;
        }
        __syncthreads();
        int excl = s_carry + (w ? ws[w - 1] : 0) + v - tsum;
        if (i4 < NI4) {
            int base = i4 * 4;
            int4 rp;
            rp.x = excl; rp.y = excl + d.x; rp.z = rp.y + d.y; rp.w = rp.z + d.z;
            *(int4*)&g_rowptr[base] = rp;
            float4 iv;
            iv.x = 1.0f / (float)max(d.x, 1);
            iv.y = 1.0f / (float)max(d.y, 1);
            iv.z = 1.0f / (float)max(d.z, 1);
            iv.w = 1.0f / (float)max(d.w, 1);
            *(float4*)&g_invdeg[base] = iv;
            deg4[i4] = make_int4(0, 0, 0, 0);   // reset for next call
            cur4[i4] = make_int4(0, 0, 0, 0);   // reset for fill
        }
        __syncthreads();
        if (t == 0) s_carry += ws[31];
        __syncthreads();
    }
    if (t == 0) g_rowptr[N_NODES] = s_carry;
}

// degree histogram (128 clamped buckets) from rowptr diffs
__global__ void dhist_kernel() {
    __shared__ int bh[128];
    int t = threadIdx.x;
    if (t < 128) bh[t] = 0;
    __syncthreads();
    int i = blockIdx.x * blockDim.x + t;
    if (i < N_NODES) {
        int d = min(g_rowptr[i + 1] - g_rowptr[i], 127);
        atomicAdd(&bh[d], 1);
    }
    __syncthreads();
    if (t < 128 && bh[t]) atomicAdd(&g_bhist[t], bh[t]);
}

// 1 block, 128 threads: exclusive scan of bucket hist + zero cursors
__global__ void bscan_kernel() {
    __shared__ int sh[128];
    int t = threadIdx.x;
    sh[t] = g_bhist[t];
    __syncthreads();
    for (int o = 1; o < 128; o <<= 1) {
        int v = (t >= o) ? sh[t - o] : 0;
        __syncthreads();
        sh[t] += v;
        __syncthreads();
    }
    g_bstart[t] = sh[t] - g_bhist[t];
    g_bcur[t] = 0;
}

// scatter node ids into degree-sorted order
__global__ void perm_kernel() {
    int i = blockIdx.x * blockDim.x + threadIdx.x;
    if (i < N_NODES) {
        int d = min(g_rowptr[i + 1] - g_rowptr[i], 127);
        int pos = atomicAdd(&g_bcur[d], 1);
        g_perm[g_bstart[d] + pos] = i;
    }
}

__global__ void fill_kernel(const void* __restrict__ ei) {
    bool is64 = detect_is64(ei);
    int i = blockIdx.x * blockDim.x + threadIdx.x;
    if (i < N_EDGES) {
        int s = load_edge(ei, i, is64);
        int d = load_edge(ei, (long long)N_EDGES + i, is64);
        if ((unsigned)d >= N_NODES || (unsigned)s >= N_NODES) return;
        int p = atomicAdd(&g_cursor[d], 1);
        g_csr[g_rowptr[d] + p] = s;
    }
}

// ---------------------------------------------------------------------------
// proj_in: x[N,4] -> inner-softmax(avg@A_in + x@B_in) [N,32] as fp16.
__global__ void __launch_bounds__(256) proj_kernel(
    const float* __restrict__ x, const float* __restrict__ Ain,
    const float* __restrict__ Bin, __half* __restrict__ out) {
    int lane = threadIdx.x & 31, wid = threadIdx.x >> 5;
    int n = blockIdx.x * 8 + wid;
    if (n >= N_NODES) return;
    int beg = g_rowptr[n], end = g_rowptr[n + 1];
    int gb = lane >> 2, ft = lane & 3;
    float sum = 0.0f;
    for (int base = beg; base < end; base += 8) {
        int j = base + gb;
        if (j < end) {
            int s = __ldg(&g_csr[j]);
            sum += __ldg(&x[s * 4 + ft]);
        }
    }
    sum += __shfl_xor_sync(0xffffffffu, sum, 4);
    sum += __shfl_xor_sync(0xffffffffu, sum, 8);
    sum += __shfl_xor_sync(0xffffffffu, sum, 16);
    float invd = g_invdeg[n];
    float a0 = __shfl_sync(0xffffffffu, sum, 0) * invd;
    float a1 = __shfl_sync(0xffffffffu, sum, 1) * invd;
    float a2 = __shfl_sync(0xffffffffu, sum, 2) * invd;
    float a3 = __shfl_sync(0xffffffffu, sum, 3) * invd;
    float4 xv = *(const float4*)&x[n * 4];
    float acc = a0 * __ldg(&Ain[lane])      + a1 * __ldg(&Ain[32 + lane])
              + a2 * __ldg(&Ain[64 + lane]) + a3 * __ldg(&Ain[96 + lane])
              + xv.x * __ldg(&Bin[lane])      + xv.y * __ldg(&Bin[32 + lane])
              + xv.z * __ldg(&Bin[64 + lane]) + xv.w * __ldg(&Bin[96 + lane]);
    float mx = acc;
#pragma unroll
    for (int o = 16; o; o >>= 1) mx = fmaxf(mx, __shfl_xor_sync(0xffffffffu, mx, o));
    float e = __expf(acc - mx);
    float ss = e;
#pragma unroll
    for (int o = 16; o; o >>= 1) ss += __shfl_xor_sync(0xffffffffu, ss, o);
    out[n * HID + lane] = __float2half_rn(e / ss);
}

// ---------------------------------------------------------------------------
// hidden conv layer, fp16 storage: 8 nodes/warp (degree-sorted via g_perm),
// 4 lanes/node, 8 feats/lane. Gather = LDG.128 with pipelined index prefetch.
__global__ void __launch_bounds__(256) conv_kernel(
    const __half* __restrict__ Ein, __half* __restrict__ Eout,
    const float* __restrict__ Wa, const float* __restrict__ Wb,
    const float* __restrict__ cs_in, float* __restrict__ cs_out) {
    __shared__ __align__(16) float sWa[HID][HID];
    __shared__ __align__(16) float sWb[HID][HID];
    __shared__ __align__(16) float sred[8][HID];
    int tid = threadIdx.x;
    int lane = tid & 31, wid = tid >> 5;
    for (int i = tid; i < HID * HID; i += 256) {
        ((float*)sWa)[i] = __ldg(&Wa[i]);
        ((float*)sWb)[i] = __ldg(&Wb[i]);
    }
    __syncthreads();

    int nid = lane >> 2;         // node slot within warp (0..7)
    int fl  = lane & 3;          // quarter-row: features fl*8 .. fl*8+7
    int nb  = lane & 28;         // node base lane

    float invS[8];
#pragma unroll
    for (int i = 0; i < 8; ++i) invS[i] = 1.0f / cs_in[fl * 8 + i];
    float colacc[8];
#pragma unroll
    for (int i = 0; i < 8; ++i) colacc[i] = 0.0f;

    for (int q = blockIdx.x * 8 + wid; q < NGRP; q += gridDim.x * 8) {
        int n = g_perm[q * 8 + nid];   // degree-sorted: all 8 have ~equal deg
        int beg = g_rowptr[n], end = g_rowptr[n + 1];
        int deg = end - beg;
        int md = deg;
        md = max(md, __shfl_xor_sync(0xffffffffu, md, 4));
        md = max(md, __shfl_xor_sync(0xffffffffu, md, 8));
        md = max(md, __shfl_xor_sync(0xffffffffu, md, 16));

        float sum[8];
#pragma unroll
        for (int i = 0; i < 8; ++i) sum[i] = 0.0f;

        const uint4* E4 = (const uint4*)Ein;
        int p0 = beg + fl;
        int idx_cur = (p0 < end) ? __ldg(&g_csr[p0]) : 0;
        for (int base = 0; base < md; base += 4) {
            int pn = beg + base + 4 + fl;
            int idx_nxt = (base + 4 < md && pn < end) ? __ldg(&g_csr[pn]) : 0;
#pragma unroll
            for (int jj = 0; jj < 4; ++jj) {
                int j = base + jj;
                int s = __shfl_sync(0xffffffffu, idx_cur, nb + jj);
                if (j < deg) {
                    uint4 v = __ldg(&E4[s * 4 + fl]);
                    float2 f0 = __half22float2(*(__half2*)&v.x);
                    float2 f1 = __half22float2(*(__half2*)&v.y);
                    float2 f2 = __half22float2(*(__half2*)&v.z);
                    float2 f3 = __half22float2(*(__half2*)&v.w);
                    sum[0] += f0.x; sum[1] += f0.y; sum[2] += f1.x; sum[3] += f1.y;
                    sum[4] += f2.x; sum[5] += f2.y; sum[6] += f3.x; sum[7] += f3.y;
                }
            }
            idx_cur = idx_nxt;
        }

        float sc = g_invdeg[n];
        uint4 vx = __ldg(&E4[n * 4 + fl]);
        float2 x0 = __half22float2(*(__half2*)&vx.x);
        float2 x1 = __half22float2(*(__half2*)&vx.y);
        float2 x2 = __half22float2(*(__half2*)&vx.z);
        float2 x3 = __half22float2(*(__half2*)&vx.w);
        float avg[8], xd[8];
        xd[0] = x0.x; xd[1] = x0.y; xd[2] = x1.x; xd[3] = x1.y;
        xd[4] = x2.x; xd[5] = x2.y; xd[6] = x3.x; xd[7] = x3.y;
#pragma unroll
        for (int i = 0; i < 8; ++i) {
            avg[i] = sum[i] * sc * invS[i];
            xd[i] *= invS[i];
        }

        float acc[8];
#pragma unroll
        for (int i = 0; i < 8; ++i) acc[i] = 0.0f;
#pragma unroll
        for (int c = 0; c < 4; ++c) {
            int src = nb + c;
#pragma unroll
            for (int j = 0; j < 8; ++j) {
                float a  = __shfl_sync(0xffffffffu, avg[j], src);
                float xv = __shfl_sync(0xffffffffu, xd[j],  src);
                int k = c * 8 + j;
                float4 wa0 = *(const float4*)&sWa[k][fl * 8];
                float4 wa1 = *(const float4*)&sWa[k][fl * 8 + 4];
                float4 wb0 = *(const float4*)&sWb[k][fl * 8];
                float4 wb1 = *(const float4*)&sWb[k][fl * 8 + 4];
                acc[0] = fmaf(a, wa0.x, acc[0]); acc[1] = fmaf(a, wa0.y, acc[1]);
                acc[2] = fmaf(a, wa0.z, acc[2]); acc[3] = fmaf(a, wa0.w, acc[3]);
                acc[4] = fmaf(a, wa1.x, acc[4]); acc[5] = fmaf(a, wa1.y, acc[5]);
                acc[6] = fmaf(a, wa1.z, acc[6]); acc[7] = fmaf(a, wa1.w, acc[7]);
                acc[0] = fmaf(xv, wb0.x, acc[0]); acc[1] = fmaf(xv, wb0.y, acc[1]);
                acc[2] = fmaf(xv, wb0.z, acc[2]); acc[3] = fmaf(xv, wb0.w, acc[3]);
                acc[4] = fmaf(xv, wb1.x, acc[4]); acc[5] = fmaf(xv, wb1.y, acc[5]);
                acc[6] = fmaf(xv, wb1.z, acc[6]); acc[7] = fmaf(xv, wb1.w, acc[7]);
            }
        }

        // inner softmax over node's 32 features (4 lanes x 8 comps)
        float mx = acc[0];
#pragma unroll
        for (int i = 1; i < 8; ++i) mx = fmaxf(mx, acc[i]);
        mx = fmaxf(mx, __shfl_xor_sync(0xffffffffu, mx, 1));
        mx = fmaxf(mx, __shfl_xor_sync(0xffffffffu, mx, 2));
        float e[8], ss = 0.0f;
#pragma unroll
        for (int i = 0; i < 8; ++i) { e[i] = __expf(acc[i] - mx); ss += e[i]; }
        ss += __shfl_xor_sync(0xffffffffu, ss, 1);
        ss += __shfl_xor_sync(0xffffffffu, ss, 2);
        float r = 1.0f / ss;
        float E[8];
#pragma unroll
        for (int i = 0; i < 8; ++i) {
            E[i] = __expf(e[i] * r);
            colacc[i] += E[i];
        }
        uint4 o;
        *(__half2*)&o.x = __floats2half2_rn(E[0], E[1]);
        *(__half2*)&o.y = __floats2half2_rn(E[2], E[3]);
        *(__half2*)&o.z = __floats2half2_rn(E[4], E[5]);
        *(__half2*)&o.w = __floats2half2_rn(E[6], E[7]);
        ((uint4*)Eout)[n * 4 + fl] = o;
    }

    // column-sum reduction: sum across the 8 node slots (lanes with same fl)
#pragma unroll
    for (int o = 4; o <= 16; o <<= 1) {
#pragma unroll
        for (int i = 0; i < 8; ++i)
            colacc[i] += __shfl_xor_sync(0xffffffffu, colacc[i], o);
    }
    if (lane < 4) {
        float4 c0 = make_float4(colacc[0], colacc[1], colacc[2], colacc[3]);
        float4 c1 = make_float4(colacc[4], colacc[5], colacc[6], colacc[7]);
        *(float4*)&sred[wid][fl * 8]     = c0;
        *(float4*)&sred[wid][fl * 8 + 4] = c1;
    }
    __syncthreads();
    if (wid == 0) {
        float t = sred[0][lane];
#pragma unroll
        for (int i = 1; i < 8; ++i) t += sred[i][lane];
        atomicAdd(&cs_out[lane], t);
    }
}

// ---------------------------------------------------------------------------
__global__ void __launch_bounds__(256) out_z_kernel(
    const __half* __restrict__ E, const float* __restrict__ cs,
    const float* __restrict__ Wout, const float* __restrict__ bout) {
    int lane = threadIdx.x & 31, wid = threadIdx.x >> 5;
    float w = __ldg(&Wout[lane]) / cs[lane];
    float b = __ldg(bout);
    float acc = 0.0f;
    for (int n = blockIdx.x * 8 + wid; n < N_NODES; n += gridDim.x * 8) {
        float v = __half2float(E[n * HID + lane]) * w;
#pragma unroll
        for (int o = 16; o; o >>= 1) v += __shfl_xor_sync(0xffffffffu, v, o);
        float e = __expf(v + b);
        if (lane == 0) { g_zexp[n] = e; acc += e; }
    }
    __shared__ float sred[8];
    if (lane == 0) sred[wid] = acc;
    __syncthreads();
    if (threadIdx.x == 0) {
        float t = 0.0f;
#pragma unroll
        for (int i = 0; i < 8; ++i) t += sred[i];
        atomicAdd(g_S, t);
    }
}

__global__ void out_norm_kernel(float* __restrict__ out) {
    int i = blockIdx.x * blockDim.x + threadIdx.x;
    if (i < N_NODES) out[i] = g_zexp[i] / g_S[0];
}

// ---------------------------------------------------------------------------
extern "C" void kernel_launch(void* const* d_in, const int* in_sizes, int n_in,
                              void* d_out, int out_size) {
    const float* x     = (const float*)d_in[0];
    const void*  ei    = d_in[1];                    // [2, N_EDGES] int32 or int64
    const float* Ain   = (const float*)d_in[2];
    const float* Bin   = (const float*)d_in[3];
    const float* Aconv = (const float*)d_in[4];      // [16,32,32]
    const float* Bconv = (const float*)d_in[5];
    const float* Wout  = (const float*)d_in[6];
    const float* bout  = (const float*)d_in[7];
    float* out         = (float*)d_out;

    __half *pA, *pB;
    float *pcs;
    cudaGetSymbolAddress((void**)&pA, g_hbufA);
    cudaGetSymbolAddress((void**)&pB, g_hbufB);
    cudaGetSymbolAddress((void**)&pcs, g_colsum);

    hist_kernel<<<(N_EDGES + 255) / 256, 256>>>(ei);
    scan_kernel<<<1, 1024>>>();
    dhist_kernel<<<(N_NODES + 255) / 256, 256>>>();
    bscan_kernel<<<1, 128>>>();
    perm_kernel<<<(N_NODES + 255) / 256, 256>>>();
    fill_kernel<<<(N_EDGES + 255) / 256, 256>>>(ei);

    proj_kernel<<<(N_NODES + 7) / 8, 256>>>(x, Ain, Bin, pA);

    __half* bi = pA;
    __half* bo = pB;
    for (int l = 0; l < NCONV; ++l) {
        conv_kernel<<<592, 256>>>(bi, bo,
                                  Aconv + l * HID * HID, Bconv + l * HID * HID,
                                  pcs + l * HID, pcs + (l + 1) * HID);
        __half* t = bi; bi = bo; bo = t;
    }

    out_z_kernel<<<592, 256>>>(bi, pcs + NCONV * HID, Wout, bout);
    out_norm_kernel<<<(N_NODES + 255) / 256, 256>>>(out);
}